// round 15
// baseline (speedup 1.0000x reference)
#include <cuda_runtime.h>
#include <cstdint>

#define Bz 32768
#define Lz 7
#define Tz 6
#define Ez 256
#define Hz 256
#define NEGV -1000000000.0f

// ---------------- tf32 / cp.async helpers ----------------
__device__ __forceinline__ uint32_t f2tf(float f) {
    uint32_t r; asm("cvt.rna.tf32.f32 %0, %1;" : "=r"(r) : "f"(f)); return r;
}
__device__ __forceinline__ void mma_tf32(float* d, uint32_t a0, uint32_t a1, uint32_t a2, uint32_t a3,
                                         uint32_t b0, uint32_t b1)
{
    asm volatile("mma.sync.aligned.m16n8k8.row.col.f32.tf32.tf32.f32 "
        "{%0,%1,%2,%3}, {%4,%5,%6,%7}, {%8,%9}, {%0,%1,%2,%3};"
        : "+f"(d[0]), "+f"(d[1]), "+f"(d[2]), "+f"(d[3])
        : "r"(a0), "r"(a1), "r"(a2), "r"(a3), "r"(b0), "r"(b1));
}
__device__ __forceinline__ void cpa16(uint32_t s, const void* g) {
    asm volatile("cp.async.cg.shared.global [%0], [%1], 16;" :: "r"(s), "l"(g));
}
#define CP_COMMIT() asm volatile("cp.async.commit_group;" ::: "memory")
#define CP_WAIT1()  asm volatile("cp.async.wait_group 1;" ::: "memory")
#define CP_WAIT0()  asm volatile("cp.async.wait_group 0;" ::: "memory")

// ---------------- static device scratch ----------------
__device__ float g_S[Bz * Hz];
__device__ float g_E4[Bz * Hz];
__device__ float g_INP[Bz * Hz];
__device__ float g_ATT[Bz * Lz];
__device__ float g_Bc[4 * Ez * Hz];
__device__ float g_Braw[4 * Ez * Hz];
__device__ float g_Bin[Ez * Hz];
__device__ float g_Bctx[Ez * Hz];
__device__ float g_colmax[Lz];
__device__ float g_colsum[Lz];
__device__ int   g_xes64;
__device__ int   g_cnt[10];
__device__ int   g_list[5 * 2 * Bz];
__device__ float g_Btf[2 * 2 * 1024 * 256];
__device__ float g_Ctf[2 * 256 * 256];

// dynamic smem layouts
#define AS_STRIDE 2560          // 128*20 floats per buffer
#define BH_STRIDE 2112          // 16*132 floats per buffer
#define STEP_SM_AS 0
#define STEP_SM_BH (2 * AS_STRIDE * 4)
#define STEP_SM_BL (STEP_SM_BH + 2 * BH_STRIDE * 4)
#define STEP_SM_IDX (STEP_SM_BL + 2 * BH_STRIDE * 4)
#define STEP_SM_TOTAL (STEP_SM_IDX + 3 * 128 * 4)          // 55808
#define ATT_SM_RED (STEP_SM_BL + 2 * BH_STRIDE * 4)
#define ATT_SM_TOTAL (ATT_SM_RED + 128 * 9 * 4)            // 58880

// ---------------- small prep kernels ----------------
__global__ void detect_xes(const int* __restrict__ xs) {
    __shared__ int any;
    if (threadIdx.x == 0) any = 0;
    __syncthreads();
    if (xs[threadIdx.x * 2 + 1] != 0) atomicOr(&any, 1);
    __syncthreads();
    if (threadIdx.x == 0) g_xes64 = any ? 0 : 1;
}

__global__ void zero_S() {
    int i = blockIdx.x * 256 + threadIdx.x;
    reinterpret_cast<float4*>(g_S)[i] = make_float4(0.f, 0.f, 0.f, 0.f);
    if (blockIdx.x == 0 && threadIdx.x < 10) g_cnt[threadIdx.x] = 0;
}

__global__ void build_lists(const void* __restrict__ xes) {
    int b = blockIdx.x * 256 + threadIdx.x;
    if (b >= Bz) return;
#pragma unroll
    for (int s = 0; s < 5; s++) {
        int c;
        if (g_xes64) {
            const long long* x = (const long long*)xes;
            c = (x[((long long)b * Tz + s) * 3 + 2] == 0) ? 1 : 0;
        } else {
            const int* x = (const int*)xes;
            c = (x[(b * Tz + s) * 3 + 2] == 0) ? 1 : 0;
        }
        int pos = atomicAdd(&g_cnt[s * 2 + c], 1);
        g_list[(s * 2 + c) * Bz + pos] = b;
    }
}

__global__ __launch_bounds__(256) void prep_compose(
    const float* __restrict__ We,
    const float* __restrict__ W0, const float* __restrict__ W1,
    const float* __restrict__ W2, const float* __restrict__ W3)
{
    int q  = blockIdx.x >> 4;
    int e0 = (blockIdx.x & 15) * 16;
    const float* Wq = (q == 0) ? W0 : (q == 1) ? W1 : (q == 2) ? W2 : W3;
    __shared__ float Ws_s[256][16];
    __shared__ float We_s[256][17];
    int tid = threadIdx.x;
    for (int it = 0; it < 16; it++) {
        int lin = it * 256 + tid;
        int j = lin >> 4, ee = lin & 15;
        Ws_s[j][ee] = Wq[j * 256 + e0 + ee];
    }
    float acc[16];
#pragma unroll
    for (int ee = 0; ee < 16; ee++) acc[ee] = 0.f;
    for (int j0 = 0; j0 < 256; j0 += 16) {
        __syncthreads();
        for (int it = 0; it < 16; it++) {
            int lin = it * 256 + tid;
            int n = lin >> 4, jj = lin & 15;
            We_s[n][jj] = We[n * 256 + j0 + jj];
        }
        __syncthreads();
#pragma unroll
        for (int jj = 0; jj < 16; jj++) {
            float we = We_s[tid][jj];
#pragma unroll
            for (int ee = 0; ee < 16; ee++)
                acc[ee] += we * Ws_s[j0 + jj][ee];
        }
    }
#pragma unroll
    for (int ee = 0; ee < 16; ee++)
        g_Bc[(q * 256 + e0 + ee) * 256 + tid] = acc[ee];
}

__global__ void prep_transpose(
    const float* __restrict__ W_h, const float* __restrict__ W_v,
    const float* __restrict__ Ws_h, const float* __restrict__ Ws_v,
    const float* __restrict__ W_in, const float* __restrict__ W_ctx)
{
    int bid = blockIdx.x;
    int matv = bid >> 8;
    int e = bid & 255;
    int n = threadIdx.x;
    const float* src = (matv == 0) ? W_h : (matv == 1) ? W_v : (matv == 2) ? Ws_h
                     : (matv == 3) ? Ws_v : (matv == 4) ? W_in : W_ctx;
    float v = src[n * 256 + e];
    if (matv < 4)        g_Braw[(matv * 256 + e) * 256 + n] = v;
    else if (matv == 4)  g_Bin[e * 256 + n] = v;
    else                 g_Bctx[e * 256 + n] = v;
}

__global__ void prep_splitTF()
{
    int k   = blockIdx.x & 1023;
    int src = blockIdx.x >> 10;
    int n   = threadIdx.x;
    float v = (src == 0 ? g_Bc : g_Braw)[k * 256 + n];
    uint32_t h = f2tf(v);
    float hf = __uint_as_float(h);
    float lo = v - hf;
    uint32_t l = f2tf(lo);
    size_t base = (size_t)src * (2 * 1024 * 256) + (size_t)k * 256 + n;
    g_Btf[base] = hf;
    g_Btf[base + 1024 * 256] = __uint_as_float(l);
}

__global__ void prep_splitCtx()
{
    int k = blockIdx.x;
    int n = threadIdx.x;
    float v = g_Bctx[k * 256 + n];
    uint32_t h = f2tf(v);
    float hf = __uint_as_float(h);
    float lo = v - hf;
    uint32_t l = f2tf(lo);
    g_Ctf[k * 256 + n] = hf;
    g_Ctf[256 * 256 + k * 256 + n] = __uint_as_float(l);
}

// ---------------- tf32 mma step GEMM (cp.async double-buffered) ----------------
#define KC 16
__global__ __launch_bounds__(256, 2)
void step_mma(const float* __restrict__ enc, const void* __restrict__ xes)
{
    int zc  = blockIdx.z;
    int cfg = zc >> 1;
    int c   = zc & 1;
    int stepi = (cfg == 5) ? 4 : cfg;
    int cnt = g_cnt[stepi * 2 + c];
    int row0 = blockIdx.y * 128;
    if (row0 >= cnt) return;
    int col0 = blockIdx.x * 128;
    const float* __restrict__ Bbase = g_Btf + (size_t)(cfg < 5 ? 0 : 1) * (2 * 1024 * 256);
    int kb = c ? 0 : 512;

    extern __shared__ char smem[];
    float* As = reinterpret_cast<float*>(smem + STEP_SM_AS);
    float* Bh = reinterpret_cast<float*>(smem + STEP_SM_BH);
    float* Bl = reinterpret_cast<float*>(smem + STEP_SM_BL);
    int* s_hoff = reinterpret_cast<int*>(smem + STEP_SM_IDX);
    int* s_voff = s_hoff + 128;
    int* s_row  = s_voff + 128;

    int tid = threadIdx.x;
    if (tid < 128) {
        int r = row0 + tid;
        int valid = (r < cnt) ? 1 : 0;
        int b = g_list[(stepi * 2 + c) * Bz + (valid ? r : row0)];
        int h, v;
        if (g_xes64) {
            const long long* x = (const long long*)xes;
            long long base = ((long long)b * Tz + stepi) * 3;
            h = (int)x[base]; v = (int)x[base + 1];
        } else {
            const int* x = (const int*)xes;
            int base = (b * Tz + stepi) * 3;
            h = x[base]; v = x[base + 1];
        }
        s_hoff[tid] = (b * Lz + h) * Ez;
        s_voff[tid] = (b * Lz + v) * Ez;
        s_row[tid] = valid ? b : -1;
    }
    __syncthreads();

    int w = tid >> 5, lane = tid & 31;
    int wm = w & 3, wn = w >> 2;
    int g = lane >> 2, tk = lane & 3;

    float acc[2][8][4];
#pragma unroll
    for (int mt = 0; mt < 2; mt++)
#pragma unroll
        for (int nt = 0; nt < 8; nt++)
#pragma unroll
            for (int q = 0; q < 4; q++) acc[mt][nt][q] = 0.f;

    int arow = tid >> 1, aks = (tid & 1) * 8;
    int bkk = tid >> 4, bn0 = (tid & 15) * 8;

    auto issue = [&](int kt, int bi) {
        const int* offs = (kt < 256) ? s_hoff : s_voff;
        const float* ap = enc + offs[arow] + (kt & 255) + aks;
        uint32_t sa = (uint32_t)__cvta_generic_to_shared(As + bi * AS_STRIDE + arow * 20 + aks);
        cpa16(sa, ap);
        cpa16(sa + 16, ap + 4);
        const float* bh = Bbase + (size_t)(kb + kt + bkk) * 256 + col0 + bn0;
        const float* bl = bh + 1024 * 256;
        uint32_t sh = (uint32_t)__cvta_generic_to_shared(Bh + bi * BH_STRIDE + bkk * 132 + bn0);
        uint32_t sl = (uint32_t)__cvta_generic_to_shared(Bl + bi * BH_STRIDE + bkk * 132 + bn0);
        cpa16(sh, bh); cpa16(sh + 16, bh + 4);
        cpa16(sl, bl); cpa16(sl + 16, bl + 4);
    };
    auto compute = [&](int bi) {
        const float* Asb = As + bi * AS_STRIDE;
        const float* Bhb = Bh + bi * BH_STRIDE;
        const float* Blb = Bl + bi * BH_STRIDE;
#pragma unroll
        for (int k8 = 0; k8 < KC; k8 += 8) {
            uint32_t ah[2][4], al[2][4];
#pragma unroll
            for (int mt = 0; mt < 2; mt++) {
                int r0 = wm * 32 + mt * 16 + g;
#pragma unroll
                for (int q = 0; q < 4; q++) {
                    int rr = r0 + (q & 1) * 8;
                    int kk = k8 + tk + (q >> 1) * 4;
                    float a = Asb[rr * 20 + kk];
                    uint32_t h = f2tf(a);
                    float lo = a - __uint_as_float(h);
                    ah[mt][q] = h;
                    al[mt][q] = f2tf(lo);
                }
            }
#pragma unroll
            for (int nt = 0; nt < 8; nt++) {
                int nn = wn * 64 + nt * 8 + g;
                uint32_t bh0 = __float_as_uint(Bhb[(k8 + tk) * 132 + nn]);
                uint32_t bh1 = __float_as_uint(Bhb[(k8 + tk + 4) * 132 + nn]);
                uint32_t bl0 = __float_as_uint(Blb[(k8 + tk) * 132 + nn]);
                uint32_t bl1 = __float_as_uint(Blb[(k8 + tk + 4) * 132 + nn]);
#pragma unroll
                for (int mt = 0; mt < 2; mt++) {
                    mma_tf32(acc[mt][nt], ah[mt][0], ah[mt][1], ah[mt][2], ah[mt][3], bh0, bh1);
                    mma_tf32(acc[mt][nt], ah[mt][0], ah[mt][1], ah[mt][2], ah[mt][3], bl0, bl1);
                    mma_tf32(acc[mt][nt], al[mt][0], al[mt][1], al[mt][2], al[mt][3], bh0, bh1);
                }
            }
        }
    };

    issue(0, 0); CP_COMMIT();
    int buf = 0;
    for (int kt = 0; kt < 512; kt += KC) {
        if (kt + KC < 512) { issue(kt + KC, buf ^ 1); CP_COMMIT(); CP_WAIT1(); }
        else CP_WAIT0();
        __syncthreads();
        compute(buf);
        __syncthreads();
        buf ^= 1;
    }

#pragma unroll
    for (int mt = 0; mt < 2; mt++) {
        int r0 = wm * 32 + mt * 16 + g;
#pragma unroll
        for (int half = 0; half < 2; half++) {
            int row = r0 + half * 8;
            int b = s_row[row];
            if (b < 0) continue;
#pragma unroll
            for (int nt = 0; nt < 8; nt++) {
                int col = col0 + wn * 64 + nt * 8 + tk * 2;
                float d0 = acc[mt][nt][half * 2 + 0];
                float d1 = acc[mt][nt][half * 2 + 1];
                if (cfg < 5) {
                    int* o = reinterpret_cast<int*>(g_S + b * 256 + col);
                    atomicMax(o + 0, __float_as_int(d0));
                    atomicMax(o + 1, __float_as_int(d1));
                } else {
                    float* o = g_E4 + b * 256 + col;
                    o[0] = d0;
                    o[1] = d1;
                }
            }
        }
    }
}

// ---------------- inp GEMM (scalar FFMA) ----------------
__global__ __launch_bounds__(256)
void inp_gemm(const float* __restrict__ b_in)
{
    __shared__ float As[16][132];
    __shared__ float Bs[16][128];
    int tid = threadIdx.x;
    int row0 = blockIdx.y * 128, col0 = blockIdx.x * 128;
    int aRow = tid >> 2, aCol = (tid & 3) << 2;
    int bRow = tid >> 5, bCol = (tid & 31) << 2;
    int tr = tid >> 4, tc = tid & 15;
    float acc[8][8];
#pragma unroll
    for (int i = 0; i < 8; i++)
#pragma unroll
        for (int j = 0; j < 8; j++) acc[i][j] = 0.f;

    for (int kt = 0; kt < 256; kt += 16) {
#pragma unroll
        for (int r = 0; r < 2; r++) {
            int m = aRow + r * 64;
            int row = row0 + m;
            float4 e4 = *reinterpret_cast<const float4*>(g_E4 + row * 256 + kt + aCol);
            float4 s4 = *reinterpret_cast<const float4*>(g_S + row * 256 + kt + aCol);
            As[aCol + 0][m] = fmaxf(e4.x + s4.x, 0.f);
            As[aCol + 1][m] = fmaxf(e4.y + s4.y, 0.f);
            As[aCol + 2][m] = fmaxf(e4.z + s4.z, 0.f);
            As[aCol + 3][m] = fmaxf(e4.w + s4.w, 0.f);
        }
#pragma unroll
        for (int r = 0; r < 2; r++) {
            int kr = bRow + r * 8;
            *reinterpret_cast<float4*>(&Bs[kr][bCol]) =
                *reinterpret_cast<const float4*>(g_Bin + (kt + kr) * 256 + col0 + bCol);
        }
        __syncthreads();
#pragma unroll
        for (int kk = 0; kk < 16; kk++) {
            float4 a0 = *reinterpret_cast<const float4*>(&As[kk][tr * 8]);
            float4 a1 = *reinterpret_cast<const float4*>(&As[kk][tr * 8 + 4]);
            float4 b0 = *reinterpret_cast<const float4*>(&Bs[kk][tc * 8]);
            float4 b1 = *reinterpret_cast<const float4*>(&Bs[kk][tc * 8 + 4]);
            float a[8] = {a0.x, a0.y, a0.z, a0.w, a1.x, a1.y, a1.z, a1.w};
            float b[8] = {b0.x, b0.y, b0.z, b0.w, b1.x, b1.y, b1.z, b1.w};
#pragma unroll
            for (int i = 0; i < 8; i++)
#pragma unroll
                for (int j = 0; j < 8; j++) acc[i][j] += a[i] * b[j];
        }
        __syncthreads();
    }
#pragma unroll
    for (int i = 0; i < 8; i++) {
        int row = row0 + tr * 8 + i;
#pragma unroll
        for (int j = 0; j < 8; j++) {
            int col = col0 + tc * 8 + j;
            g_INP[row * 256 + col] = acc[i][j] + b_in[col];
        }
    }
}

// ------- att tf32 MMA (cp.async double-buffered), fused tanh epilogue -------
__global__ __launch_bounds__(256, 2)
void att_mma(const float* __restrict__ enc, const float* __restrict__ bctx,
             const float* __restrict__ Vv, const int* __restrict__ mask)
{
    int row0 = blockIdx.x * 128;

    extern __shared__ char smem[];
    float* As = reinterpret_cast<float*>(smem + STEP_SM_AS);
    float* Bh = reinterpret_cast<float*>(smem + STEP_SM_BH);
    float* Bl = reinterpret_cast<float*>(smem + STEP_SM_BL);
    float* red = reinterpret_cast<float*>(smem + ATT_SM_RED);   // [128][9]

    int tid = threadIdx.x;
    int w = tid >> 5, lane = tid & 31;
    int wm = w & 3, wn = w >> 2;
    int g = lane >> 2, tk = lane & 3;

    for (int i = tid; i < 128 * 9; i += 256) red[i] = 0.f;
    __syncthreads();

    int arow = tid >> 1, aks = (tid & 1) * 8;
    int bkk = tid >> 4, bn0 = (tid & 15) * 8;

    for (int ct = 0; ct < 2; ct++) {
        int col0 = ct * 128;
        float acc[2][8][4];
#pragma unroll
        for (int mt = 0; mt < 2; mt++)
#pragma unroll
            for (int nt = 0; nt < 8; nt++)
#pragma unroll
                for (int q = 0; q < 4; q++) acc[mt][nt][q] = 0.f;

        auto issue = [&](int kt, int bi) {
            const float* ap = enc + (size_t)(row0 + arow) * 256 + kt + aks;
            uint32_t sa = (uint32_t)__cvta_generic_to_shared(As + bi * AS_STRIDE + arow * 20 + aks);
            cpa16(sa, ap);
            cpa16(sa + 16, ap + 4);
            const float* bh = g_Ctf + (size_t)(kt + bkk) * 256 + col0 + bn0;
            const float* bl = bh + 256 * 256;
            uint32_t sh = (uint32_t)__cvta_generic_to_shared(Bh + bi * BH_STRIDE + bkk * 132 + bn0);
            uint32_t sl = (uint32_t)__cvta_generic_to_shared(Bl + bi * BH_STRIDE + bkk * 132 + bn0);
            cpa16(sh, bh); cpa16(sh + 16, bh + 4);
            cpa16(sl, bl); cpa16(sl + 16, bl + 4);
        };
        auto compute = [&](int bi) {
            const float* Asb = As + bi * AS_STRIDE;
            const float* Bhb = Bh + bi * BH_STRIDE;
            const float* Blb = Bl + bi * BH_STRIDE;
#pragma unroll
            for (int k8 = 0; k8 < KC; k8 += 8) {
                uint32_t ah[2][4], al[2][4];
#pragma unroll
                for (int mt = 0; mt < 2; mt++) {
                    int r0 = wm * 32 + mt * 16 + g;
#pragma unroll
                    for (int q = 0; q < 4; q++) {
                        int rr = r0 + (q & 1) * 8;
                        int kk = k8 + tk + (q >> 1) * 4;
                        float a = Asb[rr * 20 + kk];
                        uint32_t h = f2tf(a);
                        float lo = a - __uint_as_float(h);
                        ah[mt][q] = h;
                        al[mt][q] = f2tf(lo);
                    }
                }
#pragma unroll
                for (int nt = 0; nt < 8; nt++) {
                    int nn = wn * 64 + nt * 8 + g;
                    uint32_t bh0 = __float_as_uint(Bhb[(k8 + tk) * 132 + nn]);
                    uint32_t bh1 = __float_as_uint(Bhb[(k8 + tk + 4) * 132 + nn]);
                    uint32_t bl0 = __float_as_uint(Blb[(k8 + tk) * 132 + nn]);
                    uint32_t bl1 = __float_as_uint(Blb[(k8 + tk + 4) * 132 + nn]);
#pragma unroll
                    for (int mt = 0; mt < 2; mt++) {
                        mma_tf32(acc[mt][nt], ah[mt][0], ah[mt][1], ah[mt][2], ah[mt][3], bh0, bh1);
                        mma_tf32(acc[mt][nt], ah[mt][0], ah[mt][1], ah[mt][2], ah[mt][3], bl0, bl1);
                        mma_tf32(acc[mt][nt], al[mt][0], al[mt][1], al[mt][2], al[mt][3], bh0, bh1);
                    }
                }
            }
        };

        issue(0, 0); CP_COMMIT();
        int buf = 0;
        for (int kt = 0; kt < 256; kt += KC) {
            if (kt + KC < 256) { issue(kt + KC, buf ^ 1); CP_COMMIT(); CP_WAIT1(); }
            else CP_WAIT0();
            __syncthreads();
            compute(buf);
            __syncthreads();
            buf ^= 1;
        }

#pragma unroll
        for (int mt = 0; mt < 2; mt++) {
#pragma unroll
            for (int half = 0; half < 2; half++) {
                int rloc = wm * 32 + mt * 16 + g + half * 8;
                int rglob = row0 + rloc;
                int b = rglob / Lz;
                const float* inprow = g_INP + b * 256;
                float s = 0.f;
#pragma unroll
                for (int nt = 0; nt < 8; nt++) {
                    int col = col0 + wn * 64 + nt * 8 + tk * 2;
                    float v0 = acc[mt][nt][half * 2 + 0] + inprow[col + 0] + bctx[col + 0];
                    float v1 = acc[mt][nt][half * 2 + 1] + inprow[col + 1] + bctx[col + 1];
                    s += Vv[col + 0] * tanhf(v0);
                    s += Vv[col + 1] * tanhf(v1);
                }
                red[rloc * 9 + wn * 4 + tk] += s;
            }
        }
    }
    __syncthreads();
    if (tid < 128) {
        float s = 0.f;
#pragma unroll
        for (int t = 0; t < 8; t++) s += red[tid * 9 + t];
        int row = row0 + tid;
        float a = mask[row] ? s : NEGV;
        g_ATT[row] = 10.f * tanhf(a);
    }
}

// ---------------- softmax stats / sampling ----------------
__global__ void col_reduce()
{
    __shared__ float sm[1024];
    int l = blockIdx.x, tid = threadIdx.x;
    float m = -1e30f;
    for (int b = tid; b < Bz; b += 1024) m = fmaxf(m, g_ATT[b * Lz + l]);
    sm[tid] = m; __syncthreads();
    for (int s = 512; s > 0; s >>= 1) { if (tid < s) sm[tid] = fmaxf(sm[tid], sm[tid + s]); __syncthreads(); }
    m = sm[0]; __syncthreads();
    float s = 0.f;
    for (int b = tid; b < Bz; b += 1024) s += expf(g_ATT[b * Lz + l] - m);
    sm[tid] = s; __syncthreads();
    for (int st = 512; st > 0; st >>= 1) { if (tid < st) sm[tid] += sm[tid + st]; __syncthreads(); }
    if (tid == 0) { g_colmax[l] = m; g_colsum[l] = sm[0]; }
}

__device__ __forceinline__ uint32_t rotl32(uint32_t x, int r) { return (x << r) | (x >> (32 - r)); }
__device__ __forceinline__ void threefry_0_42(uint32_t c0, uint32_t c1, uint32_t& o0, uint32_t& o1)
{
    const uint32_t k0 = 0u, k1 = 42u, k2 = 0u ^ 42u ^ 0x1BD11BDAu;
    uint32_t x0 = c0 + k0, x1 = c1 + k1;
#define RND(r) { x0 += x1; x1 = rotl32(x1, r); x1 ^= x0; }
    RND(13) RND(15) RND(26) RND(6)   x0 += k1; x1 += k2 + 1u;
    RND(17) RND(29) RND(16) RND(24)  x0 += k2; x1 += k0 + 2u;
    RND(13) RND(15) RND(26) RND(6)   x0 += k0; x1 += k1 + 3u;
    RND(17) RND(29) RND(16) RND(24)  x0 += k1; x1 += k2 + 4u;
    RND(13) RND(15) RND(26) RND(6)   x0 += k2; x1 += k0 + 5u;
#undef RND
    o0 = x0; o1 = x1;
}

__global__ void sample(const int* __restrict__ mask, float* __restrict__ out)
{
    int b = blockIdx.x * 256 + threadIdx.x;
    if (b >= Bz) return;
    const float TINY = 1.17549435e-38f;
    float att_r[Lz], al[Lz], la[Lz];
#pragma unroll
    for (int l = 0; l < Lz; l++) att_r[l] = g_ATT[b * Lz + l];
#pragma unroll
    for (int l = 0; l < Lz; l++) {
        float alpha = expf(att_r[l] - g_colmax[l]) / g_colsum[l];
        al[l] = alpha;
        la[l] = logf(alpha);
    }
    int best = 0; float bestv = -3.0e38f;
#pragma unroll
    for (int l = 0; l < Lz; l++) {
        uint32_t i = (uint32_t)(b * Lz + l);
        uint32_t o0, o1;
        threefry_0_42(0u, i, o0, o1);
        uint32_t bits = o0 ^ o1;
        float f = __uint_as_float((bits >> 9) | 0x3f800000u) - 1.0f;
        float u = fmaxf(TINY, f * (1.0f - TINY) + TINY);
        float g = -logf(-logf(u));
        float sc = la[l] + g;
        if (sc > bestv) { bestv = sc; best = l; }
    }
    out[b] = (float)best;
    out[Bz + b] = al[best];
#pragma unroll
    for (int l = 0; l < Lz; l++)
        out[2 * Bz + b * Lz + l] = (float)(mask[b * Lz + l] - (l == best ? 1 : 0));
}

// ---------------- launch ----------------
extern "C" void kernel_launch(void* const* d_in, const int* in_sizes, int n_in,
                              void* d_out, int out_size)
{
    const float* enc    = (const float*)d_in[0];
    const void*  xes    = d_in[1];
    const int*   mask   = (const int*)d_in[2];
    const float* W_h    = (const float*)d_in[3];
    const float* W_v    = (const float*)d_in[4];
    const float* Ws_h   = (const float*)d_in[5];
    const float* Ws_v   = (const float*)d_in[6];
    const float* W_edge = (const float*)d_in[7];
    const float* W_in   = (const float*)d_in[8];
    const float* b_in   = (const float*)d_in[9];
    const float* W_ctx  = (const float*)d_in[10];
    const float* b_ctx  = (const float*)d_in[11];
    const float* Vv     = (const float*)d_in[12];
    float* out = (float*)d_out;

    cudaFuncSetAttribute(step_mma, cudaFuncAttributeMaxDynamicSharedMemorySize, STEP_SM_TOTAL);
    cudaFuncSetAttribute(att_mma, cudaFuncAttributeMaxDynamicSharedMemorySize, ATT_SM_TOTAL);

    detect_xes<<<1, 128>>>((const int*)xes);
    zero_S<<<(Bz * Hz / 4) / 256, 256>>>();
    prep_compose<<<64, 256>>>(W_edge, W_h, W_v, Ws_h, Ws_v);
    prep_transpose<<<1536, 256>>>(W_h, W_v, Ws_h, Ws_v, W_in, W_ctx);
    prep_splitTF<<<2048, 256>>>();
    prep_splitCtx<<<256, 256>>>();
    build_lists<<<Bz / 256, 256>>>(xes);

    step_mma<<<dim3(2, 256, 12), 256, STEP_SM_TOTAL>>>(enc, xes);
    inp_gemm<<<dim3(2, 256), 256>>>(b_in);
    att_mma<<<(Bz * Lz) / 128, 256, ATT_SM_TOTAL>>>(enc, b_ctx, Vv, mask);
    col_reduce<<<Lz, 1024>>>();
    sample<<<Bz / 256, 256>>>(mask, out);
}

// round 16
// speedup vs baseline: 1.0724x; 1.0724x over previous
#include <cuda_runtime.h>
#include <cstdint>

#define Bz 32768
#define Lz 7
#define Tz 6
#define Ez 256
#define Hz 256
#define NEGV -1000000000.0f

// ---------------- tf32 helpers ----------------
__device__ __forceinline__ uint32_t f2tf(float f) {
    uint32_t r; asm("cvt.rna.tf32.f32 %0, %1;" : "=r"(r) : "f"(f)); return r;
}
__device__ __forceinline__ void mma_tf32(float* d, uint32_t a0, uint32_t a1, uint32_t a2, uint32_t a3,
                                         uint32_t b0, uint32_t b1)
{
    asm volatile("mma.sync.aligned.m16n8k8.row.col.f32.tf32.tf32.f32 "
        "{%0,%1,%2,%3}, {%4,%5,%6,%7}, {%8,%9}, {%0,%1,%2,%3};"
        : "+f"(d[0]), "+f"(d[1]), "+f"(d[2]), "+f"(d[3])
        : "r"(a0), "r"(a1), "r"(a2), "r"(a3), "r"(b0), "r"(b1));
}

// ---------------- static device scratch ----------------
__device__ float g_S[Bz * Hz];
__device__ float g_E4[Bz * Hz];
__device__ float g_INP[Bz * Hz];
__device__ float g_ATT[Bz * Lz];
__device__ float g_Bc[4 * Ez * Hz];
__device__ float g_Braw[4 * Ez * Hz];
__device__ float g_Bin[Ez * Hz];
__device__ float g_Bctx[Ez * Hz];
__device__ float g_colmax[Lz];
__device__ float g_colsum[Lz];
__device__ int   g_xes64;
__device__ int   g_cnt[10];
__device__ int   g_list[5 * 2 * Bz];
__device__ float g_Btf[2 * 2 * 1024 * 256];
__device__ float g_Ctf[2 * 256 * 256];

// ---------------- small prep kernels ----------------
__global__ void detect_xes(const int* __restrict__ xs) {
    __shared__ int any;
    if (threadIdx.x == 0) any = 0;
    __syncthreads();
    if (xs[threadIdx.x * 2 + 1] != 0) atomicOr(&any, 1);
    __syncthreads();
    if (threadIdx.x == 0) g_xes64 = any ? 0 : 1;
}

__global__ void zero_S() {
    int i = blockIdx.x * 256 + threadIdx.x;
    reinterpret_cast<float4*>(g_S)[i] = make_float4(0.f, 0.f, 0.f, 0.f);
    if (blockIdx.x == 0 && threadIdx.x < 10) g_cnt[threadIdx.x] = 0;
}

__global__ void build_lists(const void* __restrict__ xes) {
    int b = blockIdx.x * 256 + threadIdx.x;
    if (b >= Bz) return;
#pragma unroll
    for (int s = 0; s < 5; s++) {
        int c;
        if (g_xes64) {
            const long long* x = (const long long*)xes;
            c = (x[((long long)b * Tz + s) * 3 + 2] == 0) ? 1 : 0;
        } else {
            const int* x = (const int*)xes;
            c = (x[(b * Tz + s) * 3 + 2] == 0) ? 1 : 0;
        }
        int pos = atomicAdd(&g_cnt[s * 2 + c], 1);
        g_list[(s * 2 + c) * Bz + pos] = b;
    }
}

__global__ __launch_bounds__(256) void prep_compose(
    const float* __restrict__ We,
    const float* __restrict__ W0, const float* __restrict__ W1,
    const float* __restrict__ W2, const float* __restrict__ W3)
{
    int q  = blockIdx.x >> 4;
    int e0 = (blockIdx.x & 15) * 16;
    const float* Wq = (q == 0) ? W0 : (q == 1) ? W1 : (q == 2) ? W2 : W3;
    __shared__ float Ws_s[256][16];
    __shared__ float We_s[256][17];
    int tid = threadIdx.x;
    for (int it = 0; it < 16; it++) {
        int lin = it * 256 + tid;
        int j = lin >> 4, ee = lin & 15;
        Ws_s[j][ee] = Wq[j * 256 + e0 + ee];
    }
    float acc[16];
#pragma unroll
    for (int ee = 0; ee < 16; ee++) acc[ee] = 0.f;
    for (int j0 = 0; j0 < 256; j0 += 16) {
        __syncthreads();
        for (int it = 0; it < 16; it++) {
            int lin = it * 256 + tid;
            int n = lin >> 4, jj = lin & 15;
            We_s[n][jj] = We[n * 256 + j0 + jj];
        }
        __syncthreads();
#pragma unroll
        for (int jj = 0; jj < 16; jj++) {
            float we = We_s[tid][jj];
#pragma unroll
            for (int ee = 0; ee < 16; ee++)
                acc[ee] += we * Ws_s[j0 + jj][ee];
        }
    }
#pragma unroll
    for (int ee = 0; ee < 16; ee++)
        g_Bc[(q * 256 + e0 + ee) * 256 + tid] = acc[ee];
}

__global__ void prep_transpose(
    const float* __restrict__ W_h, const float* __restrict__ W_v,
    const float* __restrict__ Ws_h, const float* __restrict__ Ws_v,
    const float* __restrict__ W_in, const float* __restrict__ W_ctx)
{
    int bid = blockIdx.x;
    int matv = bid >> 8;
    int e = bid & 255;
    int n = threadIdx.x;
    const float* src = (matv == 0) ? W_h : (matv == 1) ? W_v : (matv == 2) ? Ws_h
                     : (matv == 3) ? Ws_v : (matv == 4) ? W_in : W_ctx;
    float v = src[n * 256 + e];
    if (matv < 4)        g_Braw[(matv * 256 + e) * 256 + n] = v;
    else if (matv == 4)  g_Bin[e * 256 + n] = v;
    else                 g_Bctx[e * 256 + n] = v;
}

__global__ void prep_splitTF()
{
    int k   = blockIdx.x & 1023;
    int src = blockIdx.x >> 10;
    int n   = threadIdx.x;
    float v = (src == 0 ? g_Bc : g_Braw)[k * 256 + n];
    uint32_t h = f2tf(v);
    float hf = __uint_as_float(h);
    float lo = v - hf;
    uint32_t l = f2tf(lo);
    size_t base = (size_t)src * (2 * 1024 * 256) + (size_t)k * 256 + n;
    g_Btf[base] = hf;
    g_Btf[base + 1024 * 256] = __uint_as_float(l);
}

__global__ void prep_splitCtx()
{
    int k = blockIdx.x;
    int n = threadIdx.x;
    float v = g_Bctx[k * 256 + n];
    uint32_t h = f2tf(v);
    float hf = __uint_as_float(h);
    float lo = v - hf;
    uint32_t l = f2tf(lo);
    g_Ctf[k * 256 + n] = hf;
    g_Ctf[256 * 256 + k * 256 + n] = __uint_as_float(l);
}

// ------- tf32 mma step GEMM: M=64 x N=256 per CTA (A loaded once) -------
#define KC 16
__global__ __launch_bounds__(256, 2)
void step_mma(const float* __restrict__ enc, const void* __restrict__ xes)
{
    int zc  = blockIdx.z;
    int cfg = zc >> 1;
    int c   = zc & 1;
    int stepi = (cfg == 5) ? 4 : cfg;
    int cnt = g_cnt[stepi * 2 + c];
    int row0 = blockIdx.y * 64;
    if (row0 >= cnt) return;
    const float* __restrict__ Bbase = g_Btf + (size_t)(cfg < 5 ? 0 : 1) * (2 * 1024 * 256);
    int kb = c ? 0 : 512;

    __shared__ float As[64][20];
    __shared__ float Bh[16][264];
    __shared__ float Bl[16][264];
    __shared__ int s_hoff[64], s_voff[64], s_row[64];

    int tid = threadIdx.x;
    if (tid < 64) {
        int r = row0 + tid;
        int valid = (r < cnt) ? 1 : 0;
        int b = g_list[(stepi * 2 + c) * Bz + (valid ? r : row0)];
        int h, v;
        if (g_xes64) {
            const long long* x = (const long long*)xes;
            long long base = ((long long)b * Tz + stepi) * 3;
            h = (int)x[base]; v = (int)x[base + 1];
        } else {
            const int* x = (const int*)xes;
            int base = (b * Tz + stepi) * 3;
            h = x[base]; v = x[base + 1];
        }
        s_hoff[tid] = (b * Lz + h) * Ez;
        s_voff[tid] = (b * Lz + v) * Ez;
        s_row[tid] = valid ? b : -1;
    }
    __syncthreads();

    int w = tid >> 5, lane = tid & 31;
    int wm = w & 1, wn = w >> 1;         // 2 M-warps x 4 N-warps
    int g = lane >> 2, tk = lane & 3;

    float acc[2][8][4];
#pragma unroll
    for (int mt = 0; mt < 2; mt++)
#pragma unroll
        for (int nt = 0; nt < 8; nt++)
#pragma unroll
            for (int q = 0; q < 4; q++) acc[mt][nt][q] = 0.f;

    int arow = tid >> 2, aks = (tid & 3) * 4;
    int bkk = tid >> 4, bn0 = (tid & 15) * 16;

    for (int kt = 0; kt < 512; kt += KC) {
        const int* offs = (kt < 256) ? s_hoff : s_voff;
        // A: 64 rows x 16 k (each thread one float4)
        *reinterpret_cast<float4*>(&As[arow][aks]) =
            *reinterpret_cast<const float4*>(enc + offs[arow] + (kt & 255) + aks);
        // B: 16 k x 256 n, hi+lo (each thread 4 float4 per buffer)
        {
            const float* bh = Bbase + (size_t)(kb + kt + bkk) * 256 + bn0;
            const float* bl = bh + 1024 * 256;
#pragma unroll
            for (int j = 0; j < 4; j++) {
                *reinterpret_cast<float4*>(&Bh[bkk][bn0 + j * 4]) =
                    *reinterpret_cast<const float4*>(bh + j * 4);
                *reinterpret_cast<float4*>(&Bl[bkk][bn0 + j * 4]) =
                    *reinterpret_cast<const float4*>(bl + j * 4);
            }
        }
        __syncthreads();

#pragma unroll
        for (int k8 = 0; k8 < KC; k8 += 8) {
            uint32_t ah[2][4], al[2][4];
#pragma unroll
            for (int mt = 0; mt < 2; mt++) {
                int r0 = wm * 32 + mt * 16 + g;
#pragma unroll
                for (int q = 0; q < 4; q++) {
                    int rr = r0 + (q & 1) * 8;
                    int kk = k8 + tk + (q >> 1) * 4;
                    float a = As[rr][kk];
                    uint32_t h = f2tf(a);
                    float lo = a - __uint_as_float(h);
                    ah[mt][q] = h;
                    al[mt][q] = f2tf(lo);
                }
            }
#pragma unroll
            for (int nt = 0; nt < 8; nt++) {
                int nn = wn * 64 + nt * 8 + g;
                uint32_t bh0 = __float_as_uint(Bh[k8 + tk][nn]);
                uint32_t bh1 = __float_as_uint(Bh[k8 + tk + 4][nn]);
                uint32_t bl0 = __float_as_uint(Bl[k8 + tk][nn]);
                uint32_t bl1 = __float_as_uint(Bl[k8 + tk + 4][nn]);
#pragma unroll
                for (int mt = 0; mt < 2; mt++) {
                    mma_tf32(acc[mt][nt], ah[mt][0], ah[mt][1], ah[mt][2], ah[mt][3], bh0, bh1);
                    mma_tf32(acc[mt][nt], ah[mt][0], ah[mt][1], ah[mt][2], ah[mt][3], bl0, bl1);
                    mma_tf32(acc[mt][nt], al[mt][0], al[mt][1], al[mt][2], al[mt][3], bh0, bh1);
                }
            }
        }
        __syncthreads();
    }

#pragma unroll
    for (int mt = 0; mt < 2; mt++) {
        int r0 = wm * 32 + mt * 16 + g;
#pragma unroll
        for (int half = 0; half < 2; half++) {
            int row = r0 + half * 8;
            int b = s_row[row];
            if (b < 0) continue;
#pragma unroll
            for (int nt = 0; nt < 8; nt++) {
                int col = wn * 64 + nt * 8 + tk * 2;
                float d0 = acc[mt][nt][half * 2 + 0];
                float d1 = acc[mt][nt][half * 2 + 1];
                if (cfg < 5) {
                    int* o = reinterpret_cast<int*>(g_S + b * 256 + col);
                    atomicMax(o + 0, __float_as_int(d0));
                    atomicMax(o + 1, __float_as_int(d1));
                } else {
                    float* o = g_E4 + b * 256 + col;
                    o[0] = d0;
                    o[1] = d1;
                }
            }
        }
    }
}

// ---------------- inp GEMM (scalar FFMA) ----------------
__global__ __launch_bounds__(256)
void inp_gemm(const float* __restrict__ b_in)
{
    __shared__ float As[16][132];
    __shared__ float Bs[16][128];
    int tid = threadIdx.x;
    int row0 = blockIdx.y * 128, col0 = blockIdx.x * 128;
    int aRow = tid >> 2, aCol = (tid & 3) << 2;
    int bRow = tid >> 5, bCol = (tid & 31) << 2;
    int tr = tid >> 4, tc = tid & 15;
    float acc[8][8];
#pragma unroll
    for (int i = 0; i < 8; i++)
#pragma unroll
        for (int j = 0; j < 8; j++) acc[i][j] = 0.f;

    for (int kt = 0; kt < 256; kt += 16) {
#pragma unroll
        for (int r = 0; r < 2; r++) {
            int m = aRow + r * 64;
            int row = row0 + m;
            float4 e4 = *reinterpret_cast<const float4*>(g_E4 + row * 256 + kt + aCol);
            float4 s4 = *reinterpret_cast<const float4*>(g_S + row * 256 + kt + aCol);
            As[aCol + 0][m] = fmaxf(e4.x + s4.x, 0.f);
            As[aCol + 1][m] = fmaxf(e4.y + s4.y, 0.f);
            As[aCol + 2][m] = fmaxf(e4.z + s4.z, 0.f);
            As[aCol + 3][m] = fmaxf(e4.w + s4.w, 0.f);
        }
#pragma unroll
        for (int r = 0; r < 2; r++) {
            int kr = bRow + r * 8;
            *reinterpret_cast<float4*>(&Bs[kr][bCol]) =
                *reinterpret_cast<const float4*>(g_Bin + (kt + kr) * 256 + col0 + bCol);
        }
        __syncthreads();
#pragma unroll
        for (int kk = 0; kk < 16; kk++) {
            float4 a0 = *reinterpret_cast<const float4*>(&As[kk][tr * 8]);
            float4 a1 = *reinterpret_cast<const float4*>(&As[kk][tr * 8 + 4]);
            float4 b0 = *reinterpret_cast<const float4*>(&Bs[kk][tc * 8]);
            float4 b1 = *reinterpret_cast<const float4*>(&Bs[kk][tc * 8 + 4]);
            float a[8] = {a0.x, a0.y, a0.z, a0.w, a1.x, a1.y, a1.z, a1.w};
            float b[8] = {b0.x, b0.y, b0.z, b0.w, b1.x, b1.y, b1.z, b1.w};
#pragma unroll
            for (int i = 0; i < 8; i++)
#pragma unroll
                for (int j = 0; j < 8; j++) acc[i][j] += a[i] * b[j];
        }
        __syncthreads();
    }
#pragma unroll
    for (int i = 0; i < 8; i++) {
        int row = row0 + tr * 8 + i;
#pragma unroll
        for (int j = 0; j < 8; j++) {
            int col = col0 + tc * 8 + j;
            g_INP[row * 256 + col] = acc[i][j] + b_in[col];
        }
    }
}

// ------- att tf32 MMA: M=64 x N=256 single pass, fused tanh epilogue -------
__global__ __launch_bounds__(256, 2)
void att_mma(const float* __restrict__ enc, const float* __restrict__ bctx,
             const float* __restrict__ Vv, const int* __restrict__ mask)
{
    int row0 = blockIdx.x * 64;

    __shared__ float As[64][20];
    __shared__ float Bh[16][264];
    __shared__ float Bl[16][264];
    __shared__ float red[64][17];

    int tid = threadIdx.x;
    int w = tid >> 5, lane = tid & 31;
    int wm = w & 1, wn = w >> 1;
    int g = lane >> 2, tk = lane & 3;

    float acc[2][8][4];
#pragma unroll
    for (int mt = 0; mt < 2; mt++)
#pragma unroll
        for (int nt = 0; nt < 8; nt++)
#pragma unroll
            for (int q = 0; q < 4; q++) acc[mt][nt][q] = 0.f;

    int arow = tid >> 2, aks = (tid & 3) * 4;
    int bkk = tid >> 4, bn0 = (tid & 15) * 16;

    for (int kt = 0; kt < 256; kt += KC) {
        *reinterpret_cast<float4*>(&As[arow][aks]) =
            *reinterpret_cast<const float4*>(enc + (size_t)(row0 + arow) * 256 + kt + aks);
        {
            const float* bh = g_Ctf + (size_t)(kt + bkk) * 256 + bn0;
            const float* bl = bh + 256 * 256;
#pragma unroll
            for (int j = 0; j < 4; j++) {
                *reinterpret_cast<float4*>(&Bh[bkk][bn0 + j * 4]) =
                    *reinterpret_cast<const float4*>(bh + j * 4);
                *reinterpret_cast<float4*>(&Bl[bkk][bn0 + j * 4]) =
                    *reinterpret_cast<const float4*>(bl + j * 4);
            }
        }
        __syncthreads();

#pragma unroll
        for (int k8 = 0; k8 < KC; k8 += 8) {
            uint32_t ah[2][4], al[2][4];
#pragma unroll
            for (int mt = 0; mt < 2; mt++) {
                int r0 = wm * 32 + mt * 16 + g;
#pragma unroll
                for (int q = 0; q < 4; q++) {
                    int rr = r0 + (q & 1) * 8;
                    int kk = k8 + tk + (q >> 1) * 4;
                    float a = As[rr][kk];
                    uint32_t h = f2tf(a);
                    float lo = a - __uint_as_float(h);
                    ah[mt][q] = h;
                    al[mt][q] = f2tf(lo);
                }
            }
#pragma unroll
            for (int nt = 0; nt < 8; nt++) {
                int nn = wn * 64 + nt * 8 + g;
                uint32_t bh0 = __float_as_uint(Bh[k8 + tk][nn]);
                uint32_t bh1 = __float_as_uint(Bh[k8 + tk + 4][nn]);
                uint32_t bl0 = __float_as_uint(Bl[k8 + tk][nn]);
                uint32_t bl1 = __float_as_uint(Bl[k8 + tk + 4][nn]);
#pragma unroll
                for (int mt = 0; mt < 2; mt++) {
                    mma_tf32(acc[mt][nt], ah[mt][0], ah[mt][1], ah[mt][2], ah[mt][3], bh0, bh1);
                    mma_tf32(acc[mt][nt], ah[mt][0], ah[mt][1], ah[mt][2], ah[mt][3], bl0, bl1);
                    mma_tf32(acc[mt][nt], al[mt][0], al[mt][1], al[mt][2], al[mt][3], bh0, bh1);
                }
            }
        }
        __syncthreads();
    }

    // fused epilogue: full N=256 covered in one pass
#pragma unroll
    for (int mt = 0; mt < 2; mt++) {
#pragma unroll
        for (int half = 0; half < 2; half++) {
            int rloc = wm * 32 + mt * 16 + g + half * 8;
            int rglob = row0 + rloc;
            int b = rglob / Lz;
            const float* inprow = g_INP + b * 256;
            float s = 0.f;
#pragma unroll
            for (int nt = 0; nt < 8; nt++) {
                int col = wn * 64 + nt * 8 + tk * 2;
                float v0 = acc[mt][nt][half * 2 + 0] + inprow[col + 0] + bctx[col + 0];
                float v1 = acc[mt][nt][half * 2 + 1] + inprow[col + 1] + bctx[col + 1];
                s += Vv[col + 0] * tanhf(v0);
                s += Vv[col + 1] * tanhf(v1);
            }
            red[rloc][wn * 4 + tk] = s;
        }
    }
    __syncthreads();
    if (tid < 64) {
        float s = 0.f;
#pragma unroll
        for (int t = 0; t < 16; t++) s += red[tid][t];
        int row = row0 + tid;
        float a = mask[row] ? s : NEGV;
        g_ATT[row] = 10.f * tanhf(a);
    }
}

// ---------------- softmax stats / sampling ----------------
__global__ void col_reduce()
{
    __shared__ float sm[1024];
    int l = blockIdx.x, tid = threadIdx.x;
    float m = -1e30f;
    for (int b = tid; b < Bz; b += 1024) m = fmaxf(m, g_ATT[b * Lz + l]);
    sm[tid] = m; __syncthreads();
    for (int s = 512; s > 0; s >>= 1) { if (tid < s) sm[tid] = fmaxf(sm[tid], sm[tid + s]); __syncthreads(); }
    m = sm[0]; __syncthreads();
    float s = 0.f;
    for (int b = tid; b < Bz; b += 1024) s += expf(g_ATT[b * Lz + l] - m);
    sm[tid] = s; __syncthreads();
    for (int st = 512; st > 0; st >>= 1) { if (tid < st) sm[tid] += sm[tid + st]; __syncthreads(); }
    if (tid == 0) { g_colmax[l] = m; g_colsum[l] = sm[0]; }
}

__device__ __forceinline__ uint32_t rotl32(uint32_t x, int r) { return (x << r) | (x >> (32 - r)); }
__device__ __forceinline__ void threefry_0_42(uint32_t c0, uint32_t c1, uint32_t& o0, uint32_t& o1)
{
    const uint32_t k0 = 0u, k1 = 42u, k2 = 0u ^ 42u ^ 0x1BD11BDAu;
    uint32_t x0 = c0 + k0, x1 = c1 + k1;
#define RND(r) { x0 += x1; x1 = rotl32(x1, r); x1 ^= x0; }
    RND(13) RND(15) RND(26) RND(6)   x0 += k1; x1 += k2 + 1u;
    RND(17) RND(29) RND(16) RND(24)  x0 += k2; x1 += k0 + 2u;
    RND(13) RND(15) RND(26) RND(6)   x0 += k0; x1 += k1 + 3u;
    RND(17) RND(29) RND(16) RND(24)  x0 += k1; x1 += k2 + 4u;
    RND(13) RND(15) RND(26) RND(6)   x0 += k2; x1 += k0 + 5u;
#undef RND
    o0 = x0; o1 = x1;
}

__global__ void sample(const int* __restrict__ mask, float* __restrict__ out)
{
    int b = blockIdx.x * 256 + threadIdx.x;
    if (b >= Bz) return;
    const float TINY = 1.17549435e-38f;
    float att_r[Lz], al[Lz], la[Lz];
#pragma unroll
    for (int l = 0; l < Lz; l++) att_r[l] = g_ATT[b * Lz + l];
#pragma unroll
    for (int l = 0; l < Lz; l++) {
        float alpha = expf(att_r[l] - g_colmax[l]) / g_colsum[l];
        al[l] = alpha;
        la[l] = logf(alpha);
    }
    int best = 0; float bestv = -3.0e38f;
#pragma unroll
    for (int l = 0; l < Lz; l++) {
        uint32_t i = (uint32_t)(b * Lz + l);
        uint32_t o0, o1;
        threefry_0_42(0u, i, o0, o1);
        uint32_t bits = o0 ^ o1;
        float f = __uint_as_float((bits >> 9) | 0x3f800000u) - 1.0f;
        float u = fmaxf(TINY, f * (1.0f - TINY) + TINY);
        float g = -logf(-logf(u));
        float sc = la[l] + g;
        if (sc > bestv) { bestv = sc; best = l; }
    }
    out[b] = (float)best;
    out[Bz + b] = al[best];
#pragma unroll
    for (int l = 0; l < Lz; l++)
        out[2 * Bz + b * Lz + l] = (float)(mask[b * Lz + l] - (l == best ? 1 : 0));
}

// ---------------- launch ----------------
extern "C" void kernel_launch(void* const* d_in, const int* in_sizes, int n_in,
                              void* d_out, int out_size)
{
    const float* enc    = (const float*)d_in[0];
    const void*  xes    = d_in[1];
    const int*   mask   = (const int*)d_in[2];
    const float* W_h    = (const float*)d_in[3];
    const float* W_v    = (const float*)d_in[4];
    const float* Ws_h   = (const float*)d_in[5];
    const float* Ws_v   = (const float*)d_in[6];
    const float* W_edge = (const float*)d_in[7];
    const float* W_in   = (const float*)d_in[8];
    const float* b_in   = (const float*)d_in[9];
    const float* W_ctx  = (const float*)d_in[10];
    const float* b_ctx  = (const float*)d_in[11];
    const float* Vv     = (const float*)d_in[12];
    float* out = (float*)d_out;

    detect_xes<<<1, 128>>>((const int*)xes);
    zero_S<<<(Bz * Hz / 4) / 256, 256>>>();
    prep_compose<<<64, 256>>>(W_edge, W_h, W_v, Ws_h, Ws_v);
    prep_transpose<<<1536, 256>>>(W_h, W_v, Ws_h, Ws_v, W_in, W_ctx);
    prep_splitTF<<<2048, 256>>>();
    prep_splitCtx<<<256, 256>>>();
    build_lists<<<Bz / 256, 256>>>(xes);

    step_mma<<<dim3(1, 512, 12), 256>>>(enc, xes);
    inp_gemm<<<dim3(2, 256), 256>>>(b_in);
    att_mma<<<(Bz * Lz) / 64, 256>>>(enc, b_ctx, Vv, mask);
    col_reduce<<<Lz, 1024>>>();
    sample<<<Bz / 256, 256>>>(mask, out);
}

// round 17
// speedup vs baseline: 1.4106x; 1.3154x over previous
#include <cuda_runtime.h>
#include <cstdint>

#define Bz 32768
#define Lz 7
#define Tz 6
#define Ez 256
#define Hz 256
#define NEGV -1000000000.0f

// ---------------- tf32 helpers ----------------
__device__ __forceinline__ uint32_t f2tf(float f) {
    uint32_t r; asm("cvt.rna.tf32.f32 %0, %1;" : "=r"(r) : "f"(f)); return r;
}
__device__ __forceinline__ void mma_tf32(float* d, uint32_t a0, uint32_t a1, uint32_t a2, uint32_t a3,
                                         uint32_t b0, uint32_t b1)
{
    asm volatile("mma.sync.aligned.m16n8k8.row.col.f32.tf32.tf32.f32 "
        "{%0,%1,%2,%3}, {%4,%5,%6,%7}, {%8,%9}, {%0,%1,%2,%3};"
        : "+f"(d[0]), "+f"(d[1]), "+f"(d[2]), "+f"(d[3])
        : "r"(a0), "r"(a1), "r"(a2), "r"(a3), "r"(b0), "r"(b1));
}

// ---------------- static device scratch ----------------
__device__ float g_S[Bz * Hz];
__device__ float g_E4[Bz * Hz];
__device__ float g_INP[Bz * Hz];
__device__ float g_ATT[Bz * Lz];
__device__ float g_Bc[4 * Ez * Hz];
__device__ float g_Braw[4 * Ez * Hz];
__device__ float g_Bin[Ez * Hz];
__device__ float g_Bctx[Ez * Hz];
__device__ float g_colmax[Lz];
__device__ float g_colsum[Lz];
__device__ int   g_xes64;
__device__ int   g_cnt[10];
__device__ int   g_list[5 * 2 * Bz];
__device__ float g_Btf[2 * 2 * 1024 * 256];
__device__ float g_Ctf[2 * 256 * 256];     // Wctx^T tf32 hi/lo: [hl][k][n]

// ---------------- small prep kernels ----------------
__global__ void detect_xes(const int* __restrict__ xs) {
    __shared__ int any;
    if (threadIdx.x == 0) any = 0;
    __syncthreads();
    if (xs[threadIdx.x * 2 + 1] != 0) atomicOr(&any, 1);
    __syncthreads();
    if (threadIdx.x == 0) g_xes64 = any ? 0 : 1;
}

__global__ void zero_S() {
    int i = blockIdx.x * 256 + threadIdx.x;
    reinterpret_cast<float4*>(g_S)[i] = make_float4(0.f, 0.f, 0.f, 0.f);
    if (blockIdx.x == 0 && threadIdx.x < 10) g_cnt[threadIdx.x] = 0;
}

__global__ void build_lists(const void* __restrict__ xes) {
    int b = blockIdx.x * 256 + threadIdx.x;
    if (b >= Bz) return;
#pragma unroll
    for (int s = 0; s < 5; s++) {
        int c;
        if (g_xes64) {
            const long long* x = (const long long*)xes;
            c = (x[((long long)b * Tz + s) * 3 + 2] == 0) ? 1 : 0;
        } else {
            const int* x = (const int*)xes;
            c = (x[(b * Tz + s) * 3 + 2] == 0) ? 1 : 0;
        }
        int pos = atomicAdd(&g_cnt[s * 2 + c], 1);
        g_list[(s * 2 + c) * Bz + pos] = b;
    }
}

__global__ __launch_bounds__(256) void prep_compose(
    const float* __restrict__ We,
    const float* __restrict__ W0, const float* __restrict__ W1,
    const float* __restrict__ W2, const float* __restrict__ W3)
{
    int q  = blockIdx.x >> 4;
    int e0 = (blockIdx.x & 15) * 16;
    const float* Wq = (q == 0) ? W0 : (q == 1) ? W1 : (q == 2) ? W2 : W3;
    __shared__ float Ws_s[256][16];
    __shared__ float We_s[256][17];
    int tid = threadIdx.x;
    for (int it = 0; it < 16; it++) {
        int lin = it * 256 + tid;
        int j = lin >> 4, ee = lin & 15;
        Ws_s[j][ee] = Wq[j * 256 + e0 + ee];
    }
    float acc[16];
#pragma unroll
    for (int ee = 0; ee < 16; ee++) acc[ee] = 0.f;
    for (int j0 = 0; j0 < 256; j0 += 16) {
        __syncthreads();
        for (int it = 0; it < 16; it++) {
            int lin = it * 256 + tid;
            int n = lin >> 4, jj = lin & 15;
            We_s[n][jj] = We[n * 256 + j0 + jj];
        }
        __syncthreads();
#pragma unroll
        for (int jj = 0; jj < 16; jj++) {
            float we = We_s[tid][jj];
#pragma unroll
            for (int ee = 0; ee < 16; ee++)
                acc[ee] += we * Ws_s[j0 + jj][ee];
        }
    }
#pragma unroll
    for (int ee = 0; ee < 16; ee++)
        g_Bc[(q * 256 + e0 + ee) * 256 + tid] = acc[ee];
}

__global__ void prep_transpose(
    const float* __restrict__ W_h, const float* __restrict__ W_v,
    const float* __restrict__ Ws_h, const float* __restrict__ Ws_v,
    const float* __restrict__ W_in, const float* __restrict__ W_ctx)
{
    int bid = blockIdx.x;
    int matv = bid >> 8;
    int e = bid & 255;
    int n = threadIdx.x;
    const float* src = (matv == 0) ? W_h : (matv == 1) ? W_v : (matv == 2) ? Ws_h
                     : (matv == 3) ? Ws_v : (matv == 4) ? W_in : W_ctx;
    float v = src[n * 256 + e];
    if (matv < 4)        g_Braw[(matv * 256 + e) * 256 + n] = v;
    else if (matv == 4)  g_Bin[e * 256 + n] = v;
    else                 g_Bctx[e * 256 + n] = v;
}

__global__ void prep_splitTF()
{
    int k   = blockIdx.x & 1023;
    int src = blockIdx.x >> 10;
    int n   = threadIdx.x;
    float v = (src == 0 ? g_Bc : g_Braw)[k * 256 + n];
    uint32_t h = f2tf(v);
    float hf = __uint_as_float(h);
    float lo = v - hf;
    uint32_t l = f2tf(lo);
    size_t base = (size_t)src * (2 * 1024 * 256) + (size_t)k * 256 + n;
    g_Btf[base] = hf;
    g_Btf[base + 1024 * 256] = __uint_as_float(l);
}

__global__ void prep_splitCtx()
{
    int k = blockIdx.x;
    int n = threadIdx.x;
    float v = g_Bctx[k * 256 + n];
    uint32_t h = f2tf(v);
    float hf = __uint_as_float(h);
    float lo = v - hf;
    uint32_t l = f2tf(lo);
    g_Ctf[k * 256 + n] = hf;
    g_Ctf[256 * 256 + k * 256 + n] = __uint_as_float(l);
}

// ---------------- tf32 mma step GEMM (R14 winner geometry) ----------------
#define KC 16
__global__ __launch_bounds__(256, 2)
void step_mma(const float* __restrict__ enc, const void* __restrict__ xes)
{
    int zc  = blockIdx.z;
    int cfg = zc >> 1;
    int c   = zc & 1;
    int stepi = (cfg == 5) ? 4 : cfg;
    int cnt = g_cnt[stepi * 2 + c];
    int row0 = blockIdx.y * 128;
    if (row0 >= cnt) return;
    int col0 = blockIdx.x * 128;
    const float* __restrict__ Bbase = g_Btf + (size_t)(cfg < 5 ? 0 : 1) * (2 * 1024 * 256);
    int kb = c ? 0 : 512;

    __shared__ float As[128][20];
    __shared__ float Bh[16][132];
    __shared__ float Bl[16][132];
    __shared__ int s_hoff[128], s_voff[128], s_row[128];

    int tid = threadIdx.x;
    if (tid < 128) {
        int r = row0 + tid;
        int valid = (r < cnt) ? 1 : 0;
        int b = g_list[(stepi * 2 + c) * Bz + (valid ? r : row0)];
        int h, v;
        if (g_xes64) {
            const long long* x = (const long long*)xes;
            long long base = ((long long)b * Tz + stepi) * 3;
            h = (int)x[base]; v = (int)x[base + 1];
        } else {
            const int* x = (const int*)xes;
            int base = (b * Tz + stepi) * 3;
            h = x[base]; v = x[base + 1];
        }
        s_hoff[tid] = (b * Lz + h) * Ez;
        s_voff[tid] = (b * Lz + v) * Ez;
        s_row[tid] = valid ? b : -1;
    }
    __syncthreads();

    int w = tid >> 5, lane = tid & 31;
    int wm = w & 3, wn = w >> 2;
    int g = lane >> 2, tk = lane & 3;

    float acc[2][8][4];
#pragma unroll
    for (int mt = 0; mt < 2; mt++)
#pragma unroll
        for (int nt = 0; nt < 8; nt++)
#pragma unroll
            for (int q = 0; q < 4; q++) acc[mt][nt][q] = 0.f;

    int arow = tid >> 1, aks = (tid & 1) * 8;
    int bkk = tid >> 4, bn0 = (tid & 15) * 8;

    for (int kt = 0; kt < 512; kt += KC) {
        const int* offs = (kt < 256) ? s_hoff : s_voff;
        const float* ap = enc + offs[arow] + (kt & 255) + aks;
        float4 a0 = *reinterpret_cast<const float4*>(ap);
        float4 a1 = *reinterpret_cast<const float4*>(ap + 4);
        *reinterpret_cast<float4*>(&As[arow][aks])     = a0;
        *reinterpret_cast<float4*>(&As[arow][aks + 4]) = a1;
        {
            const float* bh = Bbase + (size_t)(kb + kt + bkk) * 256 + col0 + bn0;
            const float* bl = bh + 1024 * 256;
            float4 h0 = *reinterpret_cast<const float4*>(bh);
            float4 h1 = *reinterpret_cast<const float4*>(bh + 4);
            float4 l0 = *reinterpret_cast<const float4*>(bl);
            float4 l1 = *reinterpret_cast<const float4*>(bl + 4);
            *reinterpret_cast<float4*>(&Bh[bkk][bn0])     = h0;
            *reinterpret_cast<float4*>(&Bh[bkk][bn0 + 4]) = h1;
            *reinterpret_cast<float4*>(&Bl[bkk][bn0])     = l0;
            *reinterpret_cast<float4*>(&Bl[bkk][bn0 + 4]) = l1;
        }
        __syncthreads();

#pragma unroll
        for (int k8 = 0; k8 < KC; k8 += 8) {
            uint32_t ah[2][4], al[2][4];
#pragma unroll
            for (int mt = 0; mt < 2; mt++) {
                int r0 = wm * 32 + mt * 16 + g;
#pragma unroll
                for (int q = 0; q < 4; q++) {
                    int rr = r0 + (q & 1) * 8;
                    int kk = k8 + tk + (q >> 1) * 4;
                    float a = As[rr][kk];
                    uint32_t h = f2tf(a);
                    float lo = a - __uint_as_float(h);
                    ah[mt][q] = h;
                    al[mt][q] = f2tf(lo);
                }
            }
#pragma unroll
            for (int nt = 0; nt < 8; nt++) {
                int nn = wn * 64 + nt * 8 + g;
                uint32_t bh0 = __float_as_uint(Bh[k8 + tk][nn]);
                uint32_t bh1 = __float_as_uint(Bh[k8 + tk + 4][nn]);
                uint32_t bl0 = __float_as_uint(Bl[k8 + tk][nn]);
                uint32_t bl1 = __float_as_uint(Bl[k8 + tk + 4][nn]);
#pragma unroll
                for (int mt = 0; mt < 2; mt++) {
                    mma_tf32(acc[mt][nt], ah[mt][0], ah[mt][1], ah[mt][2], ah[mt][3], bh0, bh1);
                    mma_tf32(acc[mt][nt], ah[mt][0], ah[mt][1], ah[mt][2], ah[mt][3], bl0, bl1);
                    mma_tf32(acc[mt][nt], al[mt][0], al[mt][1], al[mt][2], al[mt][3], bh0, bh1);
                }
            }
        }
        __syncthreads();
    }

#pragma unroll
    for (int mt = 0; mt < 2; mt++) {
        int r0 = wm * 32 + mt * 16 + g;
#pragma unroll
        for (int half = 0; half < 2; half++) {
            int row = r0 + half * 8;
            int b = s_row[row];
            if (b < 0) continue;
#pragma unroll
            for (int nt = 0; nt < 8; nt++) {
                int col = col0 + wn * 64 + nt * 8 + tk * 2;
                float d0 = acc[mt][nt][half * 2 + 0];
                float d1 = acc[mt][nt][half * 2 + 1];
                if (cfg < 5) {
                    int* o = reinterpret_cast<int*>(g_S + b * 256 + col);
                    atomicMax(o + 0, __float_as_int(d0));
                    atomicMax(o + 1, __float_as_int(d1));
                } else {
                    float* o = g_E4 + b * 256 + col;
                    o[0] = d0;
                    o[1] = d1;
                }
            }
        }
    }
}

// ---------------- inp GEMM (scalar FFMA; occupancy-clamped) ----------------
__global__ __launch_bounds__(256, 2)
void inp_gemm(const float* __restrict__ b_in)
{
    __shared__ float As[16][132];
    __shared__ float Bs[16][128];
    int tid = threadIdx.x;
    int row0 = blockIdx.y * 128, col0 = blockIdx.x * 128;
    int aRow = tid >> 2, aCol = (tid & 3) << 2;
    int bRow = tid >> 5, bCol = (tid & 31) << 2;
    int tr = tid >> 4, tc = tid & 15;
    float acc[8][8];
#pragma unroll
    for (int i = 0; i < 8; i++)
#pragma unroll
        for (int j = 0; j < 8; j++) acc[i][j] = 0.f;

    for (int kt = 0; kt < 256; kt += 16) {
#pragma unroll
        for (int r = 0; r < 2; r++) {
            int m = aRow + r * 64;
            int row = row0 + m;
            float4 e4 = *reinterpret_cast<const float4*>(g_E4 + row * 256 + kt + aCol);
            float4 s4 = *reinterpret_cast<const float4*>(g_S + row * 256 + kt + aCol);
            As[aCol + 0][m] = fmaxf(e4.x + s4.x, 0.f);
            As[aCol + 1][m] = fmaxf(e4.y + s4.y, 0.f);
            As[aCol + 2][m] = fmaxf(e4.z + s4.z, 0.f);
            As[aCol + 3][m] = fmaxf(e4.w + s4.w, 0.f);
        }
#pragma unroll
        for (int r = 0; r < 2; r++) {
            int kr = bRow + r * 8;
            *reinterpret_cast<float4*>(&Bs[kr][bCol]) =
                *reinterpret_cast<const float4*>(g_Bin + (kt + kr) * 256 + col0 + bCol);
        }
        __syncthreads();
#pragma unroll
        for (int kk = 0; kk < 16; kk++) {
            float4 a0 = *reinterpret_cast<const float4*>(&As[kk][tr * 8]);
            float4 a1 = *reinterpret_cast<const float4*>(&As[kk][tr * 8 + 4]);
            float4 b0 = *reinterpret_cast<const float4*>(&Bs[kk][tc * 8]);
            float4 b1 = *reinterpret_cast<const float4*>(&Bs[kk][tc * 8 + 4]);
            float a[8] = {a0.x, a0.y, a0.z, a0.w, a1.x, a1.y, a1.z, a1.w};
            float b[8] = {b0.x, b0.y, b0.z, b0.w, b1.x, b1.y, b1.z, b1.w};
#pragma unroll
            for (int i = 0; i < 8; i++)
#pragma unroll
                for (int j = 0; j < 8; j++) acc[i][j] += a[i] * b[j];
        }
        __syncthreads();
    }
#pragma unroll
    for (int i = 0; i < 8; i++) {
        int row = row0 + tr * 8 + i;
#pragma unroll
        for (int j = 0; j < 8; j++) {
            int col = col0 + tc * 8 + j;
            g_INP[row * 256 + col] = acc[i][j] + b_in[col];
        }
    }
}

// ------- att tf32 MMA (R14 winner geometry), fused tanh epilogue -------
__global__ __launch_bounds__(256, 2)
void att_mma(const float* __restrict__ enc, const float* __restrict__ bctx,
             const float* __restrict__ Vv, const int* __restrict__ mask)
{
    int row0 = blockIdx.x * 128;

    __shared__ float As[128][20];
    __shared__ float Bh[16][132];
    __shared__ float Bl[16][132];
    __shared__ float red[128][9];

    int tid = threadIdx.x;
    int w = tid >> 5, lane = tid & 31;
    int wm = w & 3, wn = w >> 2;
    int g = lane >> 2, tk = lane & 3;

    for (int i = tid; i < 128 * 9; i += 256) (&red[0][0])[i] = 0.f;

    int arow = tid >> 1, aks = (tid & 1) * 8;
    int bkk = tid >> 4, bn0 = (tid & 15) * 8;

    for (int ct = 0; ct < 2; ct++) {
        int col0 = ct * 128;
        float acc[2][8][4];
#pragma unroll
        for (int mt = 0; mt < 2; mt++)
#pragma unroll
            for (int nt = 0; nt < 8; nt++)
#pragma unroll
                for (int q = 0; q < 4; q++) acc[mt][nt][q] = 0.f;

        for (int kt = 0; kt < 256; kt += KC) {
            __syncthreads();
            const float* ap = enc + (size_t)(row0 + arow) * 256 + kt + aks;
            float4 a0 = *reinterpret_cast<const float4*>(ap);
            float4 a1 = *reinterpret_cast<const float4*>(ap + 4);
            *reinterpret_cast<float4*>(&As[arow][aks])     = a0;
            *reinterpret_cast<float4*>(&As[arow][aks + 4]) = a1;
            {
                const float* bh = g_Ctf + (size_t)(kt + bkk) * 256 + col0 + bn0;
                const float* bl = bh + 256 * 256;
                float4 h0 = *reinterpret_cast<const float4*>(bh);
                float4 h1 = *reinterpret_cast<const float4*>(bh + 4);
                float4 l0 = *reinterpret_cast<const float4*>(bl);
                float4 l1 = *reinterpret_cast<const float4*>(bl + 4);
                *reinterpret_cast<float4*>(&Bh[bkk][bn0])     = h0;
                *reinterpret_cast<float4*>(&Bh[bkk][bn0 + 4]) = h1;
                *reinterpret_cast<float4*>(&Bl[bkk][bn0])     = l0;
                *reinterpret_cast<float4*>(&Bl[bkk][bn0 + 4]) = l1;
            }
            __syncthreads();

#pragma unroll
            for (int k8 = 0; k8 < KC; k8 += 8) {
                uint32_t ah[2][4], al[2][4];
#pragma unroll
                for (int mt = 0; mt < 2; mt++) {
                    int r0 = wm * 32 + mt * 16 + g;
#pragma unroll
                    for (int q = 0; q < 4; q++) {
                        int rr = r0 + (q & 1) * 8;
                        int kk = k8 + tk + (q >> 1) * 4;
                        float a = As[rr][kk];
                        uint32_t h = f2tf(a);
                        float lo = a - __uint_as_float(h);
                        ah[mt][q] = h;
                        al[mt][q] = f2tf(lo);
                    }
                }
#pragma unroll
                for (int nt = 0; nt < 8; nt++) {
                    int nn = wn * 64 + nt * 8 + g;
                    uint32_t bh0 = __float_as_uint(Bh[k8 + tk][nn]);
                    uint32_t bh1 = __float_as_uint(Bh[k8 + tk + 4][nn]);
                    uint32_t bl0 = __float_as_uint(Bl[k8 + tk][nn]);
                    uint32_t bl1 = __float_as_uint(Bl[k8 + tk + 4][nn]);
#pragma unroll
                    for (int mt = 0; mt < 2; mt++) {
                        mma_tf32(acc[mt][nt], ah[mt][0], ah[mt][1], ah[mt][2], ah[mt][3], bh0, bh1);
                        mma_tf32(acc[mt][nt], ah[mt][0], ah[mt][1], ah[mt][2], ah[mt][3], bl0, bl1);
                        mma_tf32(acc[mt][nt], al[mt][0], al[mt][1], al[mt][2], al[mt][3], bh0, bh1);
                    }
                }
            }
        }

#pragma unroll
        for (int mt = 0; mt < 2; mt++) {
#pragma unroll
            for (int half = 0; half < 2; half++) {
                int rloc = wm * 32 + mt * 16 + g + half * 8;
                int rglob = row0 + rloc;
                int b = rglob / Lz;
                const float* inprow = g_INP + b * 256;
                float s = 0.f;
#pragma unroll
                for (int nt = 0; nt < 8; nt++) {
                    int col = col0 + wn * 64 + nt * 8 + tk * 2;
                    float v0 = acc[mt][nt][half * 2 + 0] + inprow[col + 0] + bctx[col + 0];
                    float v1 = acc[mt][nt][half * 2 + 1] + inprow[col + 1] + bctx[col + 1];
                    s += Vv[col + 0] * tanhf(v0);
                    s += Vv[col + 1] * tanhf(v1);
                }
                red[rloc][wn * 4 + tk] += s;
            }
        }
    }
    __syncthreads();
    if (tid < 128) {
        float s = 0.f;
#pragma unroll
        for (int t = 0; t < 8; t++) s += red[tid][t];
        int row = row0 + tid;
        float a = mask[row] ? s : NEGV;
        g_ATT[row] = 10.f * tanhf(a);
    }
}

// ---------------- softmax stats / sampling ----------------
__global__ void col_reduce()
{
    __shared__ float sm[1024];
    int l = blockIdx.x, tid = threadIdx.x;
    float m = -1e30f;
    for (int b = tid; b < Bz; b += 1024) m = fmaxf(m, g_ATT[b * Lz + l]);
    sm[tid] = m; __syncthreads();
    for (int s = 512; s > 0; s >>= 1) { if (tid < s) sm[tid] = fmaxf(sm[tid], sm[tid + s]); __syncthreads(); }
    m = sm[0]; __syncthreads();
    float s = 0.f;
    for (int b = tid; b < Bz; b += 1024) s += expf(g_ATT[b * Lz + l] - m);
    sm[tid] = s; __syncthreads();
    for (int st = 512; st > 0; st >>= 1) { if (tid < st) sm[tid] += sm[tid + st]; __syncthreads(); }
    if (tid == 0) { g_colmax[l] = m; g_colsum[l] = sm[0]; }
}

__device__ __forceinline__ uint32_t rotl32(uint32_t x, int r) { return (x << r) | (x >> (32 - r)); }
__device__ __forceinline__ void threefry_0_42(uint32_t c0, uint32_t c1, uint32_t& o0, uint32_t& o1)
{
    const uint32_t k0 = 0u, k1 = 42u, k2 = 0u ^ 42u ^ 0x1BD11BDAu;
    uint32_t x0 = c0 + k0, x1 = c1 + k1;
#define RND(r) { x0 += x1; x1 = rotl32(x1, r); x1 ^= x0; }
    RND(13) RND(15) RND(26) RND(6)   x0 += k1; x1 += k2 + 1u;
    RND(17) RND(29) RND(16) RND(24)  x0 += k2; x1 += k0 + 2u;
    RND(13) RND(15) RND(26) RND(6)   x0 += k0; x1 += k1 + 3u;
    RND(17) RND(29) RND(16) RND(24)  x0 += k1; x1 += k2 + 4u;
    RND(13) RND(15) RND(26) RND(6)   x0 += k2; x1 += k0 + 5u;
#undef RND
    o0 = x0; o1 = x1;
}

__global__ void sample(const int* __restrict__ mask, float* __restrict__ out)
{
    int b = blockIdx.x * 256 + threadIdx.x;
    if (b >= Bz) return;
    const float TINY = 1.17549435e-38f;
    float att_r[Lz], al[Lz], la[Lz];
#pragma unroll
    for (int l = 0; l < Lz; l++) att_r[l] = g_ATT[b * Lz + l];
#pragma unroll
    for (int l = 0; l < Lz; l++) {
        float alpha = expf(att_r[l] - g_colmax[l]) / g_colsum[l];
        al[l] = alpha;
        la[l] = logf(alpha);
    }
    int best = 0; float bestv = -3.0e38f;
#pragma unroll
    for (int l = 0; l < Lz; l++) {
        uint32_t i = (uint32_t)(b * Lz + l);
        uint32_t o0, o1;
        threefry_0_42(0u, i, o0, o1);
        uint32_t bits = o0 ^ o1;
        float f = __uint_as_float((bits >> 9) | 0x3f800000u) - 1.0f;
        float u = fmaxf(TINY, f * (1.0f - TINY) + TINY);
        float g = -logf(-logf(u));
        float sc = la[l] + g;
        if (sc > bestv) { bestv = sc; best = l; }
    }
    out[b] = (float)best;
    out[Bz + b] = al[best];
#pragma unroll
    for (int l = 0; l < Lz; l++)
        out[2 * Bz + b * Lz + l] = (float)(mask[b * Lz + l] - (l == best ? 1 : 0));
}

// ---------------- launch ----------------
extern "C" void kernel_launch(void* const* d_in, const int* in_sizes, int n_in,
                              void* d_out, int out_size)
{
    const float* enc    = (const float*)d_in[0];
    const void*  xes    = d_in[1];
    const int*   mask   = (const int*)d_in[2];
    const float* W_h    = (const float*)d_in[3];
    const float* W_v    = (const float*)d_in[4];
    const float* Ws_h   = (const float*)d_in[5];
    const float* Ws_v   = (const float*)d_in[6];
    const float* W_edge = (const float*)d_in[7];
    const float* W_in   = (const float*)d_in[8];
    const float* b_in   = (const float*)d_in[9];
    const float* W_ctx  = (const float*)d_in[10];
    const float* b_ctx  = (const float*)d_in[11];
    const float* Vv     = (const float*)d_in[12];
    float* out = (float*)d_out;

    detect_xes<<<1, 128>>>((const int*)xes);
    zero_S<<<(Bz * Hz / 4) / 256, 256>>>();
    prep_compose<<<64, 256>>>(W_edge, W_h, W_v, Ws_h, Ws_v);
    prep_transpose<<<1536, 256>>>(W_h, W_v, Ws_h, Ws_v, W_in, W_ctx);
    prep_splitTF<<<2048, 256>>>();
    prep_splitCtx<<<256, 256>>>();
    build_lists<<<Bz / 256, 256>>>(xes);

    step_mma<<<dim3(2, 256, 12), 256>>>(enc, xes);
    inp_gemm<<<dim3(2, 256), 256>>>(b_in);
    att_mma<<<(Bz * Lz) / 128, 256>>>(enc, b_ctx, Vv, mask);
    col_reduce<<<Lz, 1024>>>();
    sample<<<Bz / 256, 256>>>(mask, out);
}